// round 10
// baseline (speedup 1.0000x reference)
#include <cuda_runtime.h>
#include <cuda_bf16.h>

// Problem constants (WordSmoothCriterion: B=4, T=2048, V=32000, NNZ=801)
#define NROWS 8192
#define VDIM  32000
#define NNZ   801
#define TAU   0.8f
#define RARE  1.0f
#define ALPHA 0.7f

#define TPB    128
#define GRID   1024          // 4096 warps -> exactly 2 rows per warp
#define NWARPS (GRID * (TPB / 32))

// Scratch (device globals — allocation-free)
__device__ double g_psm[GRID];
__device__ double g_pml[GRID];
__device__ double g_pm[GRID];
__device__ unsigned int g_count = 0;   // completion counter (self-resetting)

// ---------------------------------------------------------------------------
// Warp-autonomous kernel: each warp processes whole rows independently.
// NO barriers in the main loop — warps free-run, memory demand stays
// continuous chip-wide. Row reduce = warp shuffles only.
// ---------------------------------------------------------------------------
__global__ __launch_bounds__(TPB, 7)
void ws_warp_kernel(const float* __restrict__ logp,
                    const float* __restrict__ mask,
                    const float* __restrict__ sim_values,
                    const float* __restrict__ idf_values,
                    const int*   __restrict__ target,
                    const int*   __restrict__ sim_cols,
                    float*       __restrict__ out)
{
    const int tid  = threadIdx.x;
    const int warp = tid >> 5;
    const int lane = tid & 31;
    const int gw   = blockIdx.x * (TPB / 32) + warp;   // global warp id
    const float inv_tau = 1.0f / TAU;

    // per-warp accumulators (every lane keeps a copy; lane 0's is canonical)
    double acc_sm = 0.0, acc_ml = 0.0, acc_m = 0.0;

    // exactly 2 rows per warp: n = gw, gw + NWARPS
    for (int n = gw; n < NROWS; n += NWARPS) {
        const int r = target[n];                        // broadcast load
        const float* __restrict__ lp = logp       + (size_t)n * VDIM;
        const float* __restrict__ sv = sim_values + (size_t)r * NNZ;
        const float* __restrict__ iv = idf_values + (size_t)r * NNZ;
        const int*   __restrict__ sc = sim_cols   + (size_t)r * NNZ;

        // hoisted scalar loads (uniform across warp -> single sector each)
        const float m_l = mask[n];
        const float lpr = lp[r];

        float sum_v = 0.0f, sum_gv = 0.0f;

        // lane covers j = lane + 32k, k = 0..25 (j<=831, valid while j<801).
        // 3 chunks: k in [0,9), [9,18), [18,26). Only the last chunk needs
        // predication (first invalid j = 18*32 = 576+... max valid k for
        // lane L: k=25 only when lane==0).
        #pragma unroll
        for (int ch = 0; ch < 3; ch++) {
            const int kb  = (ch == 0) ? 0 : (ch == 1 ? 9 : 18);
            const int cnt = (ch == 2) ? 8 : 9;

            int c[9]; float g[9], s[9], d[9];

            // front-batched index loads (coalesced 128B per slice)
            #pragma unroll
            for (int i = 0; i < 9; i++) {
                if (i < cnt) {
                    const int j = lane + (kb + i) * 32;
                    c[i] = (j < NNZ) ? sc[j] : 0;
                }
            }
            // up to 9 independent scattered gathers in flight
            #pragma unroll
            for (int i = 0; i < 9; i++) {
                if (i < cnt) g[i] = lp[c[i]];
            }
            // contiguous value streams
            #pragma unroll
            for (int i = 0; i < 9; i++) {
                if (i < cnt) {
                    const int j = lane + (kb + i) * 32;
                    s[i] = (j < NNZ) ? sv[j] : 0.0f;
                    d[i] = (j < NNZ) ? iv[j] : 0.0f;
                }
            }
            // math
            #pragma unroll
            for (int i = 0; i < 9; i++) {
                if (i < cnt) {
                    const int j = lane + (kb + i) * 32;
                    float val = __expf(__expf((s[i] - 1.0f - TAU * RARE * d[i]) * inv_tau) * inv_tau);
                    if (j >= NNZ) val = 0.0f;
                    sum_v  += val;
                    sum_gv += val * g[i];
                }
            }
        }

        // warp-only reduction (no smem, no barrier)
        #pragma unroll
        for (int o = 16; o > 0; o >>= 1) {
            sum_v  += __shfl_down_sync(0xffffffffu, sum_v,  o);
            sum_gv += __shfl_down_sync(0xffffffffu, sum_gv, o);
        }
        // broadcast to all lanes so accumulator stays uniform
        sum_v  = __shfl_sync(0xffffffffu, sum_v,  0);
        sum_gv = __shfl_sync(0xffffffffu, sum_gv, 0);

        acc_sm += (double)(sum_gv / sum_v);
        acc_ml += (double)(lpr * m_l);
        acc_m  += (double)m_l;
    }

    // -------- per-CTA combine (single barrier, end of kernel) --------
    __shared__ double sh[3][TPB / 32];
    __shared__ bool   s_last;
    if (lane == 0) { sh[0][warp] = acc_sm; sh[1][warp] = acc_ml; sh[2][warp] = acc_m; }
    __syncthreads();
    if (tid == 0) {
        double t_sm = 0.0, t_ml = 0.0, t_m = 0.0;
        #pragma unroll
        for (int w = 0; w < TPB / 32; w++) {           // fixed order
            t_sm += sh[0][w]; t_ml += sh[1][w]; t_m += sh[2][w];
        }
        g_psm[blockIdx.x] = t_sm;
        g_pml[blockIdx.x] = t_ml;
        g_pm[blockIdx.x]  = t_m;
        __threadfence();
        unsigned int old = atomicAdd(&g_count, 1u);
        s_last = (old == (unsigned int)(GRID - 1));
    }
    __syncthreads();

    // -------- last CTA: final deterministic reduction over GRID partials ----
    if (s_last) {
        double d_sm = 0.0, d_ml = 0.0, d_m = 0.0;
        for (int i = tid; i < GRID; i += TPB) {        // fixed strided order
            d_sm += g_psm[i];
            d_ml += g_pml[i];
            d_m  += g_pm[i];
        }
        #pragma unroll
        for (int o = 16; o > 0; o >>= 1) {
            d_sm += __shfl_down_sync(0xffffffffu, d_sm, o);
            d_ml += __shfl_down_sync(0xffffffffu, d_ml, o);
            d_m  += __shfl_down_sync(0xffffffffu, d_m,  o);
        }
        __shared__ double sh2[3][TPB / 32];
        if (lane == 0) { sh2[0][warp] = d_sm; sh2[1][warp] = d_ml; sh2[2][warp] = d_m; }
        __syncthreads();
        if (tid == 0) {
            double f_sm = 0.0, f_ml = 0.0, f_m = 0.0;
            #pragma unroll
            for (int w = 0; w < TPB / 32; w++) {
                f_sm += sh2[0][w]; f_ml += sh2[1][w]; f_m += sh2[2][w];
            }
            double smooth_loss = -f_sm / f_m;
            double ml_loss     = -f_ml / f_m;
            out[0] = (float)((double)ALPHA * smooth_loss
                             + (1.0 - (double)ALPHA) * ml_loss);
            g_count = 0;   // reset for next graph replay
        }
    }
}

// ---------------------------------------------------------------------------
extern "C" void kernel_launch(void* const* d_in, const int* in_sizes, int n_in,
                              void* d_out, int out_size)
{
    const float* logp       = (const float*)d_in[0];
    const float* mask       = (const float*)d_in[1];
    const float* sim_values = (const float*)d_in[2];
    const float* idf_values = (const float*)d_in[3];
    const int*   target     = (const int*)  d_in[4];
    const int*   sim_cols   = (const int*)  d_in[5];
    float*       out        = (float*)d_out;

    ws_warp_kernel<<<GRID, TPB>>>(logp, mask, sim_values, idf_values,
                                  target, sim_cols, out);
}

// round 11
// speedup vs baseline: 1.0424x; 1.0424x over previous
#include <cuda_runtime.h>
#include <cuda_bf16.h>

// Problem constants (WordSmoothCriterion: B=4, T=2048, V=32000, NNZ=801)
#define NROWS 8192
#define VDIM  32000
#define NNZ   801
#define TAU   0.8f
#define RARE  1.0f
#define ALPHA 0.7f

#define TPB  256
#define EPT  4          // 4*256 = 1024 >= 801 (k=3 slice predicated: tid < 33)
#define GRID 592        // 148 SMs * 4 resident CTAs -> single persistent wave

// Scratch (device globals — allocation-free)
__device__ float g_smooth[NROWS];      // per-row sum(g*sim)
__device__ float g_ml[NROWS];          // per-row lp[target]*mask
__device__ float g_maskv[NROWS];       // per-row mask
__device__ unsigned int g_work  = 0;   // work-stealing cursor (self-resetting)
__device__ unsigned int g_count = 0;   // completion counter (self-resetting)

// ---------------------------------------------------------------------------
// Persistent pipelined kernel with dynamic row claiming.
// Row->CTA mapping is nondeterministic, but results are written to per-row
// slots and reduced in fixed row order -> bitwise deterministic output.
// ---------------------------------------------------------------------------
__global__ __launch_bounds__(TPB, 4)
void ws_steal_kernel(const float* __restrict__ logp,
                     const float* __restrict__ mask,
                     const float* __restrict__ sim_values,
                     const float* __restrict__ idf_values,
                     const int*   __restrict__ target,
                     const int*   __restrict__ sim_cols,
                     float*       __restrict__ out)
{
    const int tid  = threadIdx.x;
    const int warp = tid >> 5;
    const int lane = tid & 31;
    const float inv_tau = 1.0f / TAU;
    const bool p3 = (tid < NNZ - 3 * TPB);      // k=3 slice predicate (tid < 33)

    __shared__ float s_v[8], s_gv[8];
    __shared__ int   s_next;
    __shared__ bool  s_last;

    // ---------------- prologue: claim + load first row ----------------
    if (tid == 0) s_next = (int)atomicAdd(&g_work, 1u);
    __syncthreads();
    int nA = s_next;

    int   cA[EPT];
    float sA[EPT], dA[EPT], gA[EPT];
    float mA = 0.0f, lprA = 0.0f;
    if (nA < NROWS) {
        const int rA = target[nA];
        const float* lpA = logp       + (size_t)nA * VDIM;
        const float* svA = sim_values + (size_t)rA * NNZ;
        const float* ivA = idf_values + (size_t)rA * NNZ;
        const int*   scA = sim_cols   + (size_t)rA * NNZ;
        #pragma unroll
        for (int k = 0; k < EPT; k++) {
            const bool ok = (k < 3) || p3;
            const int  j  = tid + k * TPB;
            cA[k] = ok ? scA[j] : 0;
            sA[k] = ok ? svA[j] : 0.0f;
            dA[k] = ok ? ivA[j] : 0.0f;
        }
        if (tid == 0) { mA = mask[nA]; lprA = lpA[rA]; }
        #pragma unroll
        for (int k = 0; k < EPT; k++) gA[k] = lpA[cA[k]];
    }

    // ---------------- main pipelined loop ----------------
    while (nA < NROWS) {
        // ---- claim next row ----
        if (tid == 0) s_next = (int)atomicAdd(&g_work, 1u);
        __syncthreads();                         // s_next visible; also guards
        const int  nB = s_next;                  // s_v/s_gv reuse from prev iter
        const bool hb = (nB < NROWS);

        // ---- issue next row's index/value loads ----
        int   cB[EPT];
        float sB[EPT], dB[EPT];
        float mB = 0.0f, lprB = 0.0f;
        const float* lpB = logp;
        if (hb) {
            const int rB = target[nB];
            lpB = logp + (size_t)nB * VDIM;
            const float* svB = sim_values + (size_t)rB * NNZ;
            const float* ivB = idf_values + (size_t)rB * NNZ;
            const int*   scB = sim_cols   + (size_t)rB * NNZ;
            #pragma unroll
            for (int k = 0; k < EPT; k++) {
                const bool ok = (k < 3) || p3;
                const int  j  = tid + k * TPB;
                cB[k] = ok ? scB[j] : 0;
                sB[k] = ok ? svB[j] : 0.0f;
                dB[k] = ok ? ivB[j] : 0.0f;
            }
            if (tid == 0) { mB = mask[nB]; lprB = lpB[rB]; }
        } else {
            #pragma unroll
            for (int k = 0; k < EPT; k++) { cB[k] = 0; sB[k] = 0.0f; dB[k] = 0.0f; }
        }

        // ---- compute current row ----
        float sum_v = 0.0f, sum_gv = 0.0f;
        #pragma unroll
        for (int k = 0; k < EPT; k++) {
            const bool ok = (k < 3) || p3;
            float val = __expf(__expf((sA[k] - 1.0f - TAU * RARE * dA[k]) * inv_tau) * inv_tau);
            if (!ok) val = 0.0f;
            sum_v  += val;
            sum_gv += val * gA[k];
        }

        // ---- issue next row's gathers (in flight during the reduction) ----
        float gB[EPT];
        if (hb) {
            #pragma unroll
            for (int k = 0; k < EPT; k++) gB[k] = lpB[cB[k]];
        } else {
            #pragma unroll
            for (int k = 0; k < EPT; k++) gB[k] = 0.0f;
        }

        // ---- block reduction of (sum_v, sum_gv) ----
        #pragma unroll
        for (int o = 16; o > 0; o >>= 1) {
            sum_v  += __shfl_down_sync(0xffffffffu, sum_v,  o);
            sum_gv += __shfl_down_sync(0xffffffffu, sum_gv, o);
        }
        if (lane == 0) { s_v[warp] = sum_v; s_gv[warp] = sum_gv; }
        __syncthreads();
        if (warp == 0) {
            float a = (lane < 8) ? s_v[lane]  : 0.0f;
            float b = (lane < 8) ? s_gv[lane] : 0.0f;
            #pragma unroll
            for (int o = 4; o > 0; o >>= 1) {
                a += __shfl_down_sync(0xffffffffu, a, o);
                b += __shfl_down_sync(0xffffffffu, b, o);
            }
            if (lane == 0) {
                g_smooth[nA] = b / a;            // per-row slots -> deterministic
                g_ml[nA]     = lprA * mA;
                g_maskv[nA]  = mA;
            }
        }

        // ---- rotate pipeline ----
        nA = nB;
        mA = mB; lprA = lprB;
        #pragma unroll
        for (int k = 0; k < EPT; k++) {
            cA[k] = cB[k]; sA[k] = sB[k]; dA[k] = dB[k]; gA[k] = gB[k];
        }
    }

    // ---------------- completion + last-CTA final reduction ----------------
    if (tid == 0) {
        __threadfence();
        unsigned int old = atomicAdd(&g_count, 1u);
        s_last = (old == (unsigned int)(GRID - 1));
    }
    __syncthreads();

    if (s_last) {
        double d_sm = 0.0, d_ml = 0.0, d_m = 0.0;
        for (int i = tid; i < NROWS; i += TPB) {   // fixed row order -> deterministic
            d_sm += (double)g_smooth[i];
            d_ml += (double)g_ml[i];
            d_m  += (double)g_maskv[i];
        }
        #pragma unroll
        for (int o = 16; o > 0; o >>= 1) {
            d_sm += __shfl_down_sync(0xffffffffu, d_sm, o);
            d_ml += __shfl_down_sync(0xffffffffu, d_ml, o);
            d_m  += __shfl_down_sync(0xffffffffu, d_m,  o);
        }
        __shared__ double sh[3][8];
        if (lane == 0) { sh[0][warp] = d_sm; sh[1][warp] = d_ml; sh[2][warp] = d_m; }
        __syncthreads();
        if (warp == 0) {
            d_sm = (lane < 8) ? sh[0][lane] : 0.0;
            d_ml = (lane < 8) ? sh[1][lane] : 0.0;
            d_m  = (lane < 8) ? sh[2][lane] : 0.0;
            #pragma unroll
            for (int o = 4; o > 0; o >>= 1) {
                d_sm += __shfl_down_sync(0xffffffffu, d_sm, o);
                d_ml += __shfl_down_sync(0xffffffffu, d_ml, o);
                d_m  += __shfl_down_sync(0xffffffffu, d_m,  o);
            }
            if (lane == 0) {
                double smooth_loss = -d_sm / d_m;
                double ml_loss     = -d_ml / d_m;
                out[0] = (float)((double)ALPHA * smooth_loss
                                 + (1.0 - (double)ALPHA) * ml_loss);
                g_count = 0;     // reset for next graph replay
                g_work  = 0;
            }
        }
    }
}

// ---------------------------------------------------------------------------
extern "C" void kernel_launch(void* const* d_in, const int* in_sizes, int n_in,
                              void* d_out, int out_size)
{
    const float* logp       = (const float*)d_in[0];
    const float* mask       = (const float*)d_in[1];
    const float* sim_values = (const float*)d_in[2];
    const float* idf_values = (const float*)d_in[3];
    const int*   target     = (const int*)  d_in[4];
    const int*   sim_cols   = (const int*)  d_in[5];
    float*       out        = (float*)d_out;

    ws_steal_kernel<<<GRID, TPB>>>(logp, mask, sim_values, idf_values,
                                   target, sim_cols, out);
}